// round 12
// baseline (speedup 1.0000x reference)
#include <cuda_runtime.h>

#define DIMS 2048
#define SEQ  4096
#define SENT 2.0f   // sentinel: tanh output is in (-1,1), h0 = 0 -> never 2.0

// ---------------- scratch (static device globals; no allocation) ------------
__device__ float g_A[SEQ * DIMS];                         // A = X @ W_hi^T + b
__device__ __align__(16) float g_hist[(SEQ + 1) * DIMS];  // write-once h history

// ---------------- small asm helpers -----------------------------------------
__device__ __forceinline__ float tanh_fast(float x) {
    float y;
    asm("tanh.approx.f32 %0, %1;" : "=f"(y) : "f"(x));
    return y;
}
__device__ __forceinline__ float4 ldg_vol_v4(const float4* p) {
    float4 v;
    asm volatile("ld.volatile.global.v4.f32 {%0,%1,%2,%3}, [%4];"
                 : "=f"(v.x), "=f"(v.y), "=f"(v.z), "=f"(v.w) : "l"(p));
    return v;
}
__device__ __forceinline__ void stg_vol_v4(float4* p, float4 v) {
    asm volatile("st.volatile.global.v4.f32 [%0], {%1,%2,%3,%4};"
                 :: "l"(p), "f"(v.x), "f"(v.y), "f"(v.z), "f"(v.w) : "memory");
}
// packed fp32x2 ops
__device__ __forceinline__ void ffma2(unsigned long long& d,
                                      unsigned long long a, unsigned long long b) {
    asm("fma.rn.f32x2 %0, %1, %2, %0;" : "+l"(d) : "l"(a), "l"(b));
}
__device__ __forceinline__ unsigned long long add2(unsigned long long a,
                                                   unsigned long long b) {
    unsigned long long s;
    asm("add.rn.f32x2 %0, %1, %2;" : "=l"(s) : "l"(a), "l"(b));
    return s;
}
__device__ __forceinline__ unsigned long long pack2(float x) {
    unsigned long long r;
    asm("mov.b64 %0, {%1, %1};" : "=l"(r) : "f"(x));
    return r;
}
__device__ __forceinline__ float f32x2_hsum(unsigned long long a, unsigned long long b) {
    unsigned long long s = add2(a, b);
    float2 f = *reinterpret_cast<float2*>(&s);
    return f.x + f.y;
}

// ---------------- init: poison history, seed h0 -------------------------------
__global__ void poison_kernel() {
    const float4 s = make_float4(SENT, SENT, SENT, SENT);
    float4* p = (float4*)g_hist;
    const int total = (SEQ + 1) * (DIMS / 4);
    for (int w = blockIdx.x * blockDim.x + threadIdx.x; w < total;
         w += gridDim.x * blockDim.x)
        p[w] = s;
}
__global__ void seed_kernel(const float* __restrict__ h0) {
    int i = blockIdx.x * blockDim.x + threadIdx.x;
    if (i < DIMS) g_hist[i] = h0[i];
}

// ---------------- phase 1: A = X @ W^T + b  (packed f32x2 GEMM, champion) -----
#define BM 128
#define BN 128
#define BK 8

__global__ __launch_bounds__(256) void gemm_kernel(
    const float* __restrict__ X, const float* __restrict__ W,
    const float* __restrict__ b, float* __restrict__ A)
{
    __shared__ __align__(16) float Xs[BK][BM];
    __shared__ __align__(16) float Ws[BK][BN];

    const int tid = threadIdx.x;
    const int m0  = blockIdx.y * BM;
    const int n0  = blockIdx.x * BN;
    const int tx  = tid & 15;
    const int ty  = tid >> 4;
    const int lr  = tid >> 1;
    const int lk  = (tid & 1) * 4;

    unsigned long long acc[8][4];
#pragma unroll
    for (int i = 0; i < 8; i++)
#pragma unroll
        for (int jp = 0; jp < 4; jp++) acc[i][jp] = 0ull;

    for (int k0 = 0; k0 < DIMS; k0 += BK) {
        float4 xv = *(const float4*)(X + (size_t)(m0 + lr) * DIMS + k0 + lk);
        float4 wv = *(const float4*)(W + (size_t)(n0 + lr) * DIMS + k0 + lk);
        __syncthreads();
        Xs[lk + 0][lr] = xv.x; Xs[lk + 1][lr] = xv.y;
        Xs[lk + 2][lr] = xv.z; Xs[lk + 3][lr] = xv.w;
        Ws[lk + 0][lr] = wv.x; Ws[lk + 1][lr] = wv.y;
        Ws[lk + 2][lr] = wv.z; Ws[lk + 3][lr] = wv.w;
        __syncthreads();
#pragma unroll
        for (int k = 0; k < BK; k++) {
            unsigned long long xd[8], wp[4];
#pragma unroll
            for (int i = 0; i < 8; i++) xd[i] = pack2(Xs[k][ty + 16 * i]);
#pragma unroll
            for (int jp = 0; jp < 4; jp++)
                wp[jp] = *(const unsigned long long*)&Ws[k][tx * 2 + 32 * jp];
#pragma unroll
            for (int i = 0; i < 8; i++)
#pragma unroll
                for (int jp = 0; jp < 4; jp++) ffma2(acc[i][jp], xd[i], wp[jp]);
        }
    }
    unsigned long long bp[4];
#pragma unroll
    for (int jp = 0; jp < 4; jp++)
        bp[jp] = *(const unsigned long long*)&b[n0 + tx * 2 + 32 * jp];
#pragma unroll
    for (int i = 0; i < 8; i++) {
        const int m = m0 + ty + 16 * i;
#pragma unroll
        for (int jp = 0; jp < 4; jp++) {
            *(unsigned long long*)&A[(size_t)m * DIMS + n0 + tx * 2 + 32 * jp] =
                add2(acc[i][jp], bp[jp]);
        }
    }
}

// ---------------- phase 2: persistent sequential RNN --------------------------
// Champion exchange per-thread (same poll loops, same publish). bar A replaced
// by 4 per-chunk ready counters so the dot product overlaps straggler arrival;
// each warp's W registers are pre-rotated so warps start on different chunks.
#define NCTA 128
#define RPC  16
#define RNN_THREADS 256
#define NCHUNK 4            // 4 chunks x 512 floats (128 float4 words each)

__global__ __launch_bounds__(RNN_THREADS, 1) void rnn_kernel(
    const float* __restrict__ X, const float* __restrict__ Whh,
    float* __restrict__ out)
{
    __shared__ __align__(16) float4 h_s[DIMS / 4];  // 8 KB
    __shared__ __align__(16) float  c_s[RPC];       // this CTA's 16 new h
    __shared__ int chunk_cnt[NCHUNK];               // monotonic, +4 per step

    const int tid  = threadIdx.x;
    const int wid  = tid >> 5;
    const int lane = tid & 31;
    const int cta  = blockIdx.x;
    const int row0 = cta * RPC + wid * 2;
    const int row1 = row0 + 1;
    const int cbase = wid & 3;      // rotation: warp w consumes chunks (w+s)&3

    // W_hh slice in registers, PRE-ROTATED by chunk: slot s holds the weights
    // for h-chunk (cbase+s)&3. Same 128 regs as champion.
    ulonglong2 w0[4][4], w1[4][4];
    {
        const ulonglong2* W0 = (const ulonglong2*)(Whh + (size_t)row0 * DIMS);
        const ulonglong2* W1 = (const ulonglong2*)(Whh + (size_t)row1 * DIMS);
#pragma unroll
        for (int s = 0; s < 4; s++) {
            const int c = (cbase + s) & 3;
#pragma unroll
            for (int i = 0; i < 4; i++) {
                w0[s][i] = W0[c * 128 + lane + 32 * i];
                w1[s][i] = W1[c * 128 + lane + 32 * i];
            }
        }
    }

    if (tid < NCHUNK) chunk_cnt[tid] = 0;
    __syncthreads();

    volatile int* cnt = chunk_cnt;

    for (int t = 0; t < SEQ; t++) {
        const float4* hb = (const float4*)(g_hist + (size_t)t * DIMS);
        float4*       hn = (float4*)(g_hist + (size_t)(t + 1) * DIMS);
        const int target = 4 * (t + 1);

        // Step-constant operands, off the h critical chain.
        float a0 = 0.f, a1 = 0.f, xr0 = 0.f, xr1 = 0.f;
        if (lane == 0) {
            a0  = g_A[(size_t)t * DIMS + row0];
            a1  = g_A[(size_t)t * DIMS + row1];
            xr0 = X[(size_t)t * DIMS + row0];
            xr1 = X[(size_t)t * DIMS + row1];
        }

        // ---- Stage word 1 (champion poll loop), flag its chunk ----
        // word f = tid: warps 0-3 -> chunk 0, warps 4-7 -> chunk 1.
        {
            float4 va = ldg_vol_v4(hb + tid);
            while (va.x == SENT || va.y == SENT || va.z == SENT || va.w == SENT)
                va = ldg_vol_v4(hb + tid);
            h_s[tid] = va;
        }
        __syncwarp();
        if (lane == 0) atomicAdd(&chunk_cnt[wid >> 2], 1);

        // ---- Stage word 2 (champion poll loop), flag its chunk ----
        // word f = tid + 256: warps 0-3 -> chunk 2, warps 4-7 -> chunk 3.
        {
            float4 vb = ldg_vol_v4(hb + tid + RNN_THREADS);
            while (vb.x == SENT || vb.y == SENT || vb.z == SENT || vb.w == SENT)
                vb = ldg_vol_v4(hb + tid + RNN_THREADS);
            h_s[tid + RNN_THREADS] = vb;
        }
        __syncwarp();
        if (lane == 0) atomicAdd(&chunk_cnt[2 + (wid >> 2)], 1);

        // ---- Consume chunks as they become ready (rotated start) ----
        const ulonglong2* hp = (const ulonglong2*)h_s;
        unsigned long long a0x = 0ull, a0y = 0ull, a1x = 0ull, a1y = 0ull;
#pragma unroll
        for (int s = 0; s < 4; s++) {
            const int c = (cbase + s) & 3;
            while (cnt[c] < target) { }
#pragma unroll
            for (int i = 0; i < 4; i++) {
                ulonglong2 hv = hp[c * 128 + lane + 32 * i];
                ffma2(a0x, w0[s][i].x, hv.x);  ffma2(a0y, w0[s][i].y, hv.y);
                ffma2(a1x, w1[s][i].x, hv.x);  ffma2(a1y, w1[s][i].y, hv.y);
            }
        }
        float acc0 = f32x2_hsum(a0x, a0y);
        float acc1 = f32x2_hsum(a1x, a1y);
#pragma unroll
        for (int o = 16; o > 0; o >>= 1) {
            acc0 += __shfl_xor_sync(0xffffffffu, acc0, o);
            acc1 += __shfl_xor_sync(0xffffffffu, acc1, o);
        }

        if (lane == 0) {
            float h0n = tanh_fast(a0 + acc0);
            float h1n = tanh_fast(a1 + acc1);
            c_s[wid * 2 + 0] = h0n;
            c_s[wid * 2 + 1] = h1n;
            out[(size_t)t * DIMS + row0] = xr0 + h0n;   // residual, off-chain
            out[(size_t)t * DIMS + row1] = xr1 + h1n;
        }
        __syncthreads();   // bar B (kept): c_s complete, h_s reads done,
                           // warps phase-locked before next step's polls

        // ---- Publish: byte-identical to champion ----
        if (tid < 4) stg_vol_v4(hn + cta * 4 + tid, *(const float4*)&c_s[tid * 4]);
    }
}

// ---------------- launch -------------------------------------------------------
extern "C" void kernel_launch(void* const* d_in, const int* in_sizes, int n_in,
                              void* d_out, int out_size) {
    const float* X    = (const float*)d_in[0];  // [SEQ, DIMS]
    const float* W_hi = (const float*)d_in[1];  // [DIMS, DIMS]
    const float* W_hh = (const float*)d_in[2];  // [DIMS, DIMS]
    const float* b    = (const float*)d_in[3];  // [DIMS]
    const float* h0   = (const float*)d_in[4];  // [DIMS]
    float* out = (float*)d_out;

    float* A;
    cudaGetSymbolAddress((void**)&A, g_A);

    poison_kernel<<<1024, 256>>>();
    seed_kernel<<<(DIMS + 255) / 256, 256>>>(h0);

    dim3 ggrid(DIMS / BN, SEQ / BM);            // (16, 32)
    gemm_kernel<<<ggrid, 256>>>(X, W_hi, b, A);

    rnn_kernel<<<NCTA, RNN_THREADS>>>(X, W_hh, out);
}